// round 1
// baseline (speedup 1.0000x reference)
#include <cuda_runtime.h>
#include <cstdint>

// Problem constants (fixed by the dataset)
#define NNODE 50000
#define NEDGE 800000
#define FIN   128
#define FH    256
#define FOUT  10
#define NG    512

// ---------------- scratch (device globals; no allocation) ----------------
__device__ float4 g_agg1[NNODE * (FIN / 4)];   // 25.6 MB
__device__ float4 g_t1  [NNODE * (FH  / 4)];   // 51.2 MB
__device__ float4 g_h   [NNODE * (FH  / 4)];
__device__ float4 g_agg2[NNODE * (FH  / 4)];
__device__ float4 g_t2  [NNODE * (FH  / 4)];
__device__ float4 g_h2  [NNODE * (FH  / 4)];
__device__ float4 g_psum[NG * (FH / 4)];
__device__ float  g_cnt [NG];

// ---------------- small utility kernels ----------------
__global__ void zero_k(float* __restrict__ p, int n) {
    int i = blockIdx.x * blockDim.x + threadIdx.x;
    if (i < n) p[i] = 0.0f;
}

// out[i] = (1 + *eps) * x[i]   (vectorized float4)
__global__ void scale_copy_k(const float4* __restrict__ x, const float* __restrict__ eps,
                             float4* __restrict__ out, int total) {
    int i = blockIdx.x * blockDim.x + threadIdx.x;
    if (i >= total) return;
    float s = 1.0f + *eps;
    float4 v = x[i];
    out[i] = make_float4(v.x * s, v.y * s, v.z * s, v.w * s);
}

// Edge scatter-add: out[dst[e]] += feat[src[e]]  (float4 atomics, sm_90+)
__global__ void scatter_k(const float4* __restrict__ feat, const int* __restrict__ src,
                          const int* __restrict__ dst, float4* __restrict__ out,
                          int total, int shift, int mask, int f4) {
    int i = blockIdx.x * blockDim.x + threadIdx.x;
    if (i >= total) return;
    int e = i >> shift;
    int f = i & mask;
    int s = src[e];
    int d = dst[e];
    atomicAdd(&out[d * f4 + f], feat[(size_t)s * f4 + f]);
}

// ---------------- SGEMM: C[M,256] = A[M,K] @ B[K,256] + bias, opt ReLU,
// opt dual store C2 = (1+eps)*C.  128x128 tile, BK=8, 8x8 per thread. ----------------
template <bool RELU, bool DUAL>
__global__ __launch_bounds__(256, 2)
void gemm_k(const float* __restrict__ A, const float* __restrict__ B,
            const float* __restrict__ bias, float* __restrict__ C,
            float* __restrict__ C2, const float* __restrict__ epsp,
            int M, int K) {
    const int NCOL = 256;
    __shared__ float As[8][128];
    __shared__ float Bs[8][128];

    int tid = threadIdx.x;
    int tx = tid & 15;        // 0..15 -> 8 cols each
    int ty = tid >> 4;        // 0..15 -> 8 rows each
    int m0 = blockIdx.y * 128;
    int n0 = blockIdx.x * 128;

    int arow  = tid >> 1;       // 0..127
    int acol4 = (tid & 1) * 4;  // 0 or 4
    int brow  = tid >> 5;       // 0..7
    int bcol4 = (tid & 31) * 4; // 0..124

    float acc[8][8];
#pragma unroll
    for (int i = 0; i < 8; i++)
#pragma unroll
        for (int j = 0; j < 8; j++) acc[i][j] = 0.0f;

    for (int k0 = 0; k0 < K; k0 += 8) {
        float4 av;
        if (m0 + arow < M)
            av = *(const float4*)&A[(size_t)(m0 + arow) * K + k0 + acol4];
        else
            av = make_float4(0.f, 0.f, 0.f, 0.f);
        As[acol4 + 0][arow] = av.x;
        As[acol4 + 1][arow] = av.y;
        As[acol4 + 2][arow] = av.z;
        As[acol4 + 3][arow] = av.w;

        float4 bv = *(const float4*)&B[(size_t)(k0 + brow) * NCOL + n0 + bcol4];
        *(float4*)&Bs[brow][bcol4] = bv;

        __syncthreads();
#pragma unroll
        for (int kk = 0; kk < 8; kk++) {
            float a[8], b[8];
            *(float4*)&a[0] = *(const float4*)&As[kk][ty * 8];
            *(float4*)&a[4] = *(const float4*)&As[kk][ty * 8 + 4];
            *(float4*)&b[0] = *(const float4*)&Bs[kk][tx * 8];
            *(float4*)&b[4] = *(const float4*)&Bs[kk][tx * 8 + 4];
#pragma unroll
            for (int i = 0; i < 8; i++)
#pragma unroll
                for (int j = 0; j < 8; j++) acc[i][j] += a[i] * b[j];
        }
        __syncthreads();
    }

    float scale = DUAL ? (1.0f + *epsp) : 1.0f;
#pragma unroll
    for (int i = 0; i < 8; i++) {
        int row = m0 + ty * 8 + i;
        if (row >= M) break;
#pragma unroll
        for (int j = 0; j < 8; j++) {
            int col = n0 + tx * 8 + j;
            float v = acc[i][j] + bias[col];
            if (RELU) v = fmaxf(v, 0.0f);
            C[(size_t)row * NCOL + col] = v;
            if (DUAL) C2[(size_t)row * NCOL + col] = v * scale;
        }
    }
}

// ---------------- pooling ----------------
__global__ void pool_k(const float4* __restrict__ h2, const int* __restrict__ batch,
                       float4* __restrict__ psum) {
    int i = blockIdx.x * blockDim.x + threadIdx.x;  // over NNODE * (FH/4)
    if (i >= NNODE * (FH / 4)) return;
    int n = i >> 6;   // FH/4 = 64
    int f = i & 63;
    atomicAdd(&psum[batch[n] * 64 + f], h2[i]);
}

__global__ void count_k(const int* __restrict__ batch, float* __restrict__ cnt) {
    int i = blockIdx.x * blockDim.x + threadIdx.x;
    if (i < NNODE) atomicAdd(&cnt[batch[i]], 1.0f);
}

// ---------------- final: mean, linear [256->10], log_softmax ----------------
__global__ void final_k(const float* __restrict__ psum, const float* __restrict__ cnt,
                        const float* __restrict__ Wlin, const float* __restrict__ blin,
                        float* __restrict__ out) {
    int g = blockIdx.x;
    int lane = threadIdx.x;
    float inv = 1.0f / fmaxf(cnt[g], 1.0f);
    float acc[FOUT];
#pragma unroll
    for (int o = 0; o < FOUT; o++) acc[o] = 0.0f;
    for (int h = lane; h < FH; h += 32) {
        float p = psum[g * FH + h] * inv;
#pragma unroll
        for (int o = 0; o < FOUT; o++) acc[o] += p * Wlin[h * FOUT + o];
    }
#pragma unroll
    for (int off = 16; off > 0; off >>= 1)
#pragma unroll
        for (int o = 0; o < FOUT; o++)
            acc[o] += __shfl_down_sync(0xffffffffu, acc[o], off);
    if (lane == 0) {
        float z[FOUT];
        float m = -1e30f;
#pragma unroll
        for (int o = 0; o < FOUT; o++) { z[o] = acc[o] + blin[o]; m = fmaxf(m, z[o]); }
        float s = 0.0f;
#pragma unroll
        for (int o = 0; o < FOUT; o++) s += __expf(z[o] - m);
        float l = logf(s);
#pragma unroll
        for (int o = 0; o < FOUT; o++) out[g * FOUT + o] = z[o] - m - l;
    }
}

// ---------------- launcher ----------------
extern "C" void kernel_launch(void* const* d_in, const int* in_sizes, int n_in,
                              void* d_out, int out_size) {
    const float* x     = (const float*)d_in[0];
    const int*   ei    = (const int*)  d_in[1];   // [2, E]: src = ei, dst = ei + E
    const int*   batch = (const int*)  d_in[2];
    const float* eps1  = (const float*)d_in[3];
    const float* W1a   = (const float*)d_in[4];
    const float* b1a   = (const float*)d_in[5];
    const float* W1b   = (const float*)d_in[6];
    const float* b1b   = (const float*)d_in[7];
    const float* eps2  = (const float*)d_in[8];
    const float* W2a   = (const float*)d_in[9];
    const float* b2a   = (const float*)d_in[10];
    const float* W2b   = (const float*)d_in[11];
    const float* b2b   = (const float*)d_in[12];
    const float* Wlin  = (const float*)d_in[13];
    const float* blin  = (const float*)d_in[14];
    float* out = (float*)d_out;

    void *p_agg1, *p_t1, *p_h, *p_agg2, *p_t2, *p_h2, *p_psum, *p_cnt;
    cudaGetSymbolAddress(&p_agg1, g_agg1);
    cudaGetSymbolAddress(&p_t1,   g_t1);
    cudaGetSymbolAddress(&p_h,    g_h);
    cudaGetSymbolAddress(&p_agg2, g_agg2);
    cudaGetSymbolAddress(&p_t2,   g_t2);
    cudaGetSymbolAddress(&p_h2,   g_h2);
    cudaGetSymbolAddress(&p_psum, g_psum);
    cudaGetSymbolAddress(&p_cnt,  g_cnt);
    float4* agg1 = (float4*)p_agg1;
    float4* t1   = (float4*)p_t1;
    float4* h    = (float4*)p_h;
    float4* agg2 = (float4*)p_agg2;
    float4* t2   = (float4*)p_t2;
    float4* h2   = (float4*)p_h2;
    float4* psum = (float4*)p_psum;
    float*  cnt  = (float*)p_cnt;

    const int* src = ei;
    const int* dst = ei + NEDGE;
    const int T = 256;

    // agg1 = (1+eps1)*x, then += sum_{edges} x[src]
    {
        int total = NNODE * (FIN / 4);
        scale_copy_k<<<(total + T - 1) / T, T>>>((const float4*)x, eps1, agg1, total);
    }
    {
        int total = NEDGE * (FIN / 4);  // shift=5, mask=31, f4=32
        scatter_k<<<(total + T - 1) / T, T>>>((const float4*)x, src, dst, agg1,
                                              total, 5, 31, FIN / 4);
    }

    dim3 gdim(2, (NNODE + 127) / 128);
    // t1 = relu(agg1 @ W1a + b1a)
    gemm_k<true, false><<<gdim, 256>>>((const float*)agg1, W1a, b1a,
                                       (float*)t1, nullptr, nullptr, NNODE, FIN);
    // h = relu(t1 @ W1b + b1b);  agg2 = (1+eps2)*h   (fused dual store)
    gemm_k<true, true><<<gdim, 256>>>((const float*)t1, W1b, b1b,
                                      (float*)h, (float*)agg2, eps2, NNODE, FH);
    // agg2 += sum_{edges} h[src]
    {
        int total = NEDGE * (FH / 4);  // shift=6, mask=63, f4=64
        scatter_k<<<(total + T - 1) / T, T>>>(h, src, dst, agg2, total, 6, 63, FH / 4);
    }
    // t2 = relu(agg2 @ W2a + b2a)
    gemm_k<true, false><<<gdim, 256>>>((const float*)agg2, W2a, b2a,
                                       (float*)t2, nullptr, nullptr, NNODE, FH);
    // h2 = t2 @ W2b + b2b
    gemm_k<false, false><<<gdim, 256>>>((const float*)t2, W2b, b2b,
                                        (float*)h2, nullptr, nullptr, NNODE, FH);

    // pooling
    zero_k<<<(NG * FH + T - 1) / T, T>>>((float*)psum, NG * FH);
    zero_k<<<(NG + T - 1) / T, T>>>(cnt, NG);
    {
        int total = NNODE * (FH / 4);
        pool_k<<<(total + T - 1) / T, T>>>(h2, batch, psum);
    }
    count_k<<<(NNODE + T - 1) / T, T>>>(batch, cnt);

    // mean + linear + log_softmax
    final_k<<<NG, 32>>>((const float*)psum, cnt, Wlin, blin, out);
}

// round 2
// speedup vs baseline: 1.5220x; 1.5220x over previous
#include <cuda_runtime.h>
#include <mma.h>
#include <cstdint>

using namespace nvcuda;

// Problem constants (fixed by the dataset)
#define NNODE 50000
#define NEDGE 800000
#define FIN   128
#define FH    256
#define FOUT  10
#define NG    512

// ---------------- scratch (device globals; no allocation) ----------------
__device__ float4 g_agg1[NNODE * (FIN / 4)];   // 25.6 MB
__device__ float4 g_t1  [NNODE * (FH  / 4)];   // 51.2 MB
__device__ float4 g_h   [NNODE * (FH  / 4)];
__device__ float4 g_agg2[NNODE * (FH  / 4)];
__device__ float4 g_t2  [NNODE * (FH  / 4)];
__device__ float4 g_h2  [NNODE * (FH  / 4)];
__device__ float4 g_psum[NG * (FH / 4)];
__device__ float  g_cnt [NG];

// ---------------- small utility kernels ----------------
__global__ void zero_k(float* __restrict__ p, int n) {
    int i = blockIdx.x * blockDim.x + threadIdx.x;
    if (i < n) p[i] = 0.0f;
}

// out[i] = (1 + *eps) * x[i]   (vectorized float4)
__global__ void scale_copy_k(const float4* __restrict__ x, const float* __restrict__ eps,
                             float4* __restrict__ out, int total) {
    int i = blockIdx.x * blockDim.x + threadIdx.x;
    if (i >= total) return;
    float s = 1.0f + *eps;
    float4 v = x[i];
    out[i] = make_float4(v.x * s, v.y * s, v.z * s, v.w * s);
}

// Edge scatter-add: out[dst[e]] += feat[src[e]]  (float4 atomics, sm_90+)
__global__ void scatter_k(const float4* __restrict__ feat, const int* __restrict__ src,
                          const int* __restrict__ dst, float4* __restrict__ out,
                          int total, int shift, int mask, int f4) {
    int i = blockIdx.x * blockDim.x + threadIdx.x;
    if (i >= total) return;
    int e = i >> shift;
    int f = i & mask;
    int s = src[e];
    int d = dst[e];
    atomicAdd(&out[d * f4 + f], feat[(size_t)s * f4 + f]);
}

// ---------------- Tensor-core TF32 GEMM ----------------
// C[M,256] = A[M,K] @ B[K,256] + bias, optional ReLU,
// optional dual store C2 = (1+eps)*C.
// Block tile 128x128, BK=32, 8 warps (4x2), warp tile 32x64 (2x4 wmma frags).
template <bool RELU, bool DUAL>
__global__ __launch_bounds__(256, 2)
void gemm_tc(const float* __restrict__ A, const float* __restrict__ B,
             const float* __restrict__ bias, float* __restrict__ C,
             float* __restrict__ C2, const float* __restrict__ epsp,
             int M, int K) {
    constexpr int LDA = 36;    // 32 + pad (mult of 4)
    constexpr int LDB = 132;   // 128 + pad (mult of 4)
    constexpr int LDS_ = 20;   // 16 + pad (mult of 4)
    __shared__ float As[128 * LDA];       // 18 KB
    __shared__ float Bs[32 * LDB];        // 16.5 KB
    __shared__ float St[8][16 * LDS_];    // 10 KB

    int tid  = threadIdx.x;
    int wid  = tid >> 5;
    int lane = tid & 31;
    int wm = wid >> 1;          // 0..3  -> warp row tile (32 rows)
    int wn = wid & 1;           // 0..1  -> warp col tile (64 cols)
    int m0 = blockIdx.y * 128;
    int n0 = blockIdx.x * 128;

    wmma::fragment<wmma::accumulator, 16, 16, 8, float> acc[2][4];
#pragma unroll
    for (int i = 0; i < 2; i++)
#pragma unroll
        for (int j = 0; j < 4; j++) wmma::fill_fragment(acc[i][j], 0.0f);

    for (int k0 = 0; k0 < K; k0 += 32) {
        // ---- load A tile 128x32 (row-major, tf32-converted) ----
#pragma unroll
        for (int t = 0; t < 4; t++) {
            int j   = tid + t * 256;          // 0..1023 float4 slots
            int row = j >> 3;                 // 0..127
            int c4  = (j & 7) * 4;            // 0..28
            float4 v = make_float4(0.f, 0.f, 0.f, 0.f);
            if (m0 + row < M)
                v = *(const float4*)&A[(size_t)(m0 + row) * K + k0 + c4];
            float* d = &As[row * LDA + c4];
            d[0] = wmma::__float_to_tf32(v.x);
            d[1] = wmma::__float_to_tf32(v.y);
            d[2] = wmma::__float_to_tf32(v.z);
            d[3] = wmma::__float_to_tf32(v.w);
        }
        // ---- load B tile 32x128 (row-major, tf32-converted) ----
#pragma unroll
        for (int t = 0; t < 4; t++) {
            int j   = tid + t * 256;
            int row = j >> 5;                 // 0..31
            int c4  = (j & 31) * 4;           // 0..124
            float4 v = *(const float4*)&B[(size_t)(k0 + row) * 256 + n0 + c4];
            float* d = &Bs[row * LDB + c4];
            d[0] = wmma::__float_to_tf32(v.x);
            d[1] = wmma::__float_to_tf32(v.y);
            d[2] = wmma::__float_to_tf32(v.z);
            d[3] = wmma::__float_to_tf32(v.w);
        }
        __syncthreads();

#pragma unroll
        for (int ks = 0; ks < 4; ks++) {
            wmma::fragment<wmma::matrix_a, 16, 16, 8, wmma::precision::tf32,
                           wmma::row_major> af[2];
            wmma::fragment<wmma::matrix_b, 16, 16, 8, wmma::precision::tf32,
                           wmma::row_major> bf[4];
#pragma unroll
            for (int i = 0; i < 2; i++)
                wmma::load_matrix_sync(af[i], &As[(wm * 32 + i * 16) * LDA + ks * 8], LDA);
#pragma unroll
            for (int j = 0; j < 4; j++)
                wmma::load_matrix_sync(bf[j], &Bs[(ks * 8) * LDB + wn * 64 + j * 16], LDB);
#pragma unroll
            for (int i = 0; i < 2; i++)
#pragma unroll
                for (int j = 0; j < 4; j++)
                    wmma::mma_sync(acc[i][j], af[i], bf[j], acc[i][j]);
        }
        __syncthreads();
    }

    // ---- epilogue: bias (+ReLU) (+dual scaled store) via per-warp smem staging ----
    float scale = DUAL ? (1.0f + *epsp) : 1.0f;
#pragma unroll
    for (int i = 0; i < 2; i++)
#pragma unroll
        for (int j = 0; j < 4; j++) {
            wmma::store_matrix_sync(&St[wid][0], acc[i][j], LDS_, wmma::mem_row_major);
            __syncwarp();
            int r   = lane >> 1;              // 0..15
            int c   = (lane & 1) * 8;         // 0 or 8
            int row = m0 + wm * 32 + i * 16 + r;
            int col = n0 + wn * 64 + j * 16 + c;
            if (row < M) {
                float v[8];
#pragma unroll
                for (int u = 0; u < 8; u++) {
                    v[u] = St[wid][r * LDS_ + c + u] + bias[col + u];
                    if (RELU) v[u] = fmaxf(v[u], 0.0f);
                }
                float4* cp = (float4*)&C[(size_t)row * 256 + col];
                cp[0] = make_float4(v[0], v[1], v[2], v[3]);
                cp[1] = make_float4(v[4], v[5], v[6], v[7]);
                if (DUAL) {
                    float4* cp2 = (float4*)&C2[(size_t)row * 256 + col];
                    cp2[0] = make_float4(v[0] * scale, v[1] * scale, v[2] * scale, v[3] * scale);
                    cp2[1] = make_float4(v[4] * scale, v[5] * scale, v[6] * scale, v[7] * scale);
                }
            }
            __syncwarp();
        }
}

// ---------------- pooling ----------------
__global__ void pool_k(const float4* __restrict__ h2, const int* __restrict__ batch,
                       float4* __restrict__ psum) {
    int i = blockIdx.x * blockDim.x + threadIdx.x;  // over NNODE * (FH/4)
    if (i >= NNODE * (FH / 4)) return;
    int n = i >> 6;   // FH/4 = 64
    int f = i & 63;
    atomicAdd(&psum[batch[n] * 64 + f], h2[i]);
}

__global__ void count_k(const int* __restrict__ batch, float* __restrict__ cnt) {
    int i = blockIdx.x * blockDim.x + threadIdx.x;
    if (i < NNODE) atomicAdd(&cnt[batch[i]], 1.0f);
}

// ---------------- final: mean, linear [256->10], log_softmax ----------------
__global__ void final_k(const float* __restrict__ psum, const float* __restrict__ cnt,
                        const float* __restrict__ Wlin, const float* __restrict__ blin,
                        float* __restrict__ out) {
    int g = blockIdx.x;
    int lane = threadIdx.x;
    float inv = 1.0f / fmaxf(cnt[g], 1.0f);
    float acc[FOUT];
#pragma unroll
    for (int o = 0; o < FOUT; o++) acc[o] = 0.0f;
    for (int h = lane; h < FH; h += 32) {
        float p = psum[g * FH + h] * inv;
#pragma unroll
        for (int o = 0; o < FOUT; o++) acc[o] += p * Wlin[h * FOUT + o];
    }
#pragma unroll
    for (int off = 16; off > 0; off >>= 1)
#pragma unroll
        for (int o = 0; o < FOUT; o++)
            acc[o] += __shfl_down_sync(0xffffffffu, acc[o], off);
    if (lane == 0) {
        float z[FOUT];
        float m = -1e30f;
#pragma unroll
        for (int o = 0; o < FOUT; o++) { z[o] = acc[o] + blin[o]; m = fmaxf(m, z[o]); }
        float s = 0.0f;
#pragma unroll
        for (int o = 0; o < FOUT; o++) s += __expf(z[o] - m);
        float l = logf(s);
#pragma unroll
        for (int o = 0; o < FOUT; o++) out[g * FOUT + o] = z[o] - m - l;
    }
}

// ---------------- launcher ----------------
extern "C" void kernel_launch(void* const* d_in, const int* in_sizes, int n_in,
                              void* d_out, int out_size) {
    const float* x     = (const float*)d_in[0];
    const int*   ei    = (const int*)  d_in[1];   // [2, E]: src = ei, dst = ei + E
    const int*   batch = (const int*)  d_in[2];
    const float* eps1  = (const float*)d_in[3];
    const float* W1a   = (const float*)d_in[4];
    const float* b1a   = (const float*)d_in[5];
    const float* W1b   = (const float*)d_in[6];
    const float* b1b   = (const float*)d_in[7];
    const float* eps2  = (const float*)d_in[8];
    const float* W2a   = (const float*)d_in[9];
    const float* b2a   = (const float*)d_in[10];
    const float* W2b   = (const float*)d_in[11];
    const float* b2b   = (const float*)d_in[12];
    const float* Wlin  = (const float*)d_in[13];
    const float* blin  = (const float*)d_in[14];
    float* out = (float*)d_out;

    void *p_agg1, *p_t1, *p_h, *p_agg2, *p_t2, *p_h2, *p_psum, *p_cnt;
    cudaGetSymbolAddress(&p_agg1, g_agg1);
    cudaGetSymbolAddress(&p_t1,   g_t1);
    cudaGetSymbolAddress(&p_h,    g_h);
    cudaGetSymbolAddress(&p_agg2, g_agg2);
    cudaGetSymbolAddress(&p_t2,   g_t2);
    cudaGetSymbolAddress(&p_h2,   g_h2);
    cudaGetSymbolAddress(&p_psum, g_psum);
    cudaGetSymbolAddress(&p_cnt,  g_cnt);
    float4* agg1 = (float4*)p_agg1;
    float4* t1   = (float4*)p_t1;
    float4* h    = (float4*)p_h;
    float4* agg2 = (float4*)p_agg2;
    float4* t2   = (float4*)p_t2;
    float4* h2   = (float4*)p_h2;
    float4* psum = (float4*)p_psum;
    float*  cnt  = (float*)p_cnt;

    const int* src = ei;
    const int* dst = ei + NEDGE;
    const int T = 256;

    // agg1 = (1+eps1)*x, then += sum_{edges} x[src]
    {
        int total = NNODE * (FIN / 4);
        scale_copy_k<<<(total + T - 1) / T, T>>>((const float4*)x, eps1, agg1, total);
    }
    {
        int total = NEDGE * (FIN / 4);  // shift=5, mask=31, f4=32
        scatter_k<<<(total + T - 1) / T, T>>>((const float4*)x, src, dst, agg1,
                                              total, 5, 31, FIN / 4);
    }

    dim3 gdim(2, (NNODE + 127) / 128);
    // t1 = relu(agg1 @ W1a + b1a)
    gemm_tc<true, false><<<gdim, 256>>>((const float*)agg1, W1a, b1a,
                                        (float*)t1, nullptr, nullptr, NNODE, FIN);
    // h = relu(t1 @ W1b + b1b);  agg2 = (1+eps2)*h   (fused dual store)
    gemm_tc<true, true><<<gdim, 256>>>((const float*)t1, W1b, b1b,
                                       (float*)h, (float*)agg2, eps2, NNODE, FH);
    // agg2 += sum_{edges} h[src]
    {
        int total = NEDGE * (FH / 4);  // shift=6, mask=63, f4=64
        scatter_k<<<(total + T - 1) / T, T>>>(h, src, dst, agg2, total, 6, 63, FH / 4);
    }
    // t2 = relu(agg2 @ W2a + b2a)
    gemm_tc<true, false><<<gdim, 256>>>((const float*)agg2, W2a, b2a,
                                        (float*)t2, nullptr, nullptr, NNODE, FH);
    // h2 = t2 @ W2b + b2b
    gemm_tc<false, false><<<gdim, 256>>>((const float*)t2, W2b, b2b,
                                         (float*)h2, nullptr, nullptr, NNODE, FH);

    // pooling
    zero_k<<<(NG * FH + T - 1) / T, T>>>((float*)psum, NG * FH);
    zero_k<<<(NG + T - 1) / T, T>>>(cnt, NG);
    {
        int total = NNODE * (FH / 4);
        pool_k<<<(total + T - 1) / T, T>>>(h2, batch, psum);
    }
    count_k<<<(NNODE + T - 1) / T, T>>>(batch, cnt);

    // mean + linear + log_softmax
    final_k<<<NG, 32>>>((const float*)psum, cnt, Wlin, blin, out);
}

// round 4
// speedup vs baseline: 1.5537x; 1.0208x over previous
#include <cuda_runtime.h>
#include <mma.h>
#include <cstdint>

using namespace nvcuda;

// Problem constants (fixed by the dataset)
#define NNODE 50000
#define NEDGE 800000
#define FIN   128
#define FH    256
#define FOUT  10
#define NG    512

// ---------------- scratch (device globals; no allocation) ----------------
__device__ float4 g_agg1[NNODE * (FIN / 4)];   // 25.6 MB
__device__ float4 g_t1  [NNODE * (FH  / 4)];   // 51.2 MB
__device__ float4 g_h   [NNODE * (FH  / 4)];
__device__ float4 g_agg2[NNODE * (FH  / 4)];
__device__ float4 g_t2  [NNODE * (FH  / 4)];
__device__ float4 g_psum[NG * (FH / 4)];
__device__ float  g_cnt [NG];
// tf32-preconverted weights
__device__ float  g_W1a_t[FIN * FH];
__device__ float  g_W1b_t[FH * FH];
__device__ float  g_W2a_t[FH * FH];
__device__ float  g_W2b_t[FH * FH];

// ---------------- cp.async helpers ----------------
__device__ __forceinline__ void cp_async16(float* dst, const float* src) {
    uint32_t s = (uint32_t)__cvta_generic_to_shared(dst);
    asm volatile("cp.async.cg.shared.global [%0], [%1], 16;\n" :: "r"(s), "l"(src));
}
__device__ __forceinline__ void cp_async16z(float* dst, const float* src, int szbytes) {
    uint32_t s = (uint32_t)__cvta_generic_to_shared(dst);
    asm volatile("cp.async.cg.shared.global [%0], [%1], 16, %2;\n"
                 :: "r"(s), "l"(src), "r"(szbytes));
}
__device__ __forceinline__ void cp_commit() { asm volatile("cp.async.commit_group;\n"); }
template <int N>
__device__ __forceinline__ void cp_wait() { asm volatile("cp.async.wait_group %0;\n" :: "n"(N)); }

// ---------------- small utility kernels ----------------
__global__ void zero_k(float* __restrict__ p, int n) {
    int i = blockIdx.x * blockDim.x + threadIdx.x;
    if (i < n) p[i] = 0.0f;
}

__global__ void wconv_k(const float* __restrict__ src, float* __restrict__ dst, int n) {
    int i = blockIdx.x * blockDim.x + threadIdx.x;
    if (i < n) dst[i] = wmma::__float_to_tf32(src[i]);
}

// out[i] = (1 + *eps) * x[i]
__global__ void scale_copy_k(const float4* __restrict__ x, const float* __restrict__ eps,
                             float4* __restrict__ out, int total) {
    int i = blockIdx.x * blockDim.x + threadIdx.x;
    if (i >= total) return;
    float s = 1.0f + *eps;
    float4 v = x[i];
    out[i] = make_float4(v.x * s, v.y * s, v.z * s, v.w * s);
}

// Edge scatter-add: out[dst[e]] += feat[src[e]]  (float4 atomics)
__global__ void scatter_k(const float4* __restrict__ feat, const int* __restrict__ src,
                          const int* __restrict__ dst, float4* __restrict__ out,
                          int total, int shift, int mask, int f4) {
    int i = blockIdx.x * blockDim.x + threadIdx.x;
    if (i >= total) return;
    int e = i >> shift;
    int f = i & mask;
    int s = src[e];
    int d = dst[e];
    atomicAdd(&out[d * f4 + f], feat[(size_t)s * f4 + f]);
}

__global__ void count_k(const int* __restrict__ batch, float* __restrict__ cnt) {
    int i = blockIdx.x * blockDim.x + threadIdx.x;
    if (i < NNODE) atomicAdd(&cnt[batch[i]], 1.0f);
}

// ---------------- Pipelined TF32 tensor-core GEMM ----------------
// C[M,256] = A[M,K] @ B[K,256] + bias; B pre-converted to tf32.
// RELU: relu epilogue.  DUAL: also C2 = (1+eps)*C.  POOL: no C store,
// atomicAdd rows into psum[batch[row]*256 + col].
// 128x128 tile, BK=32, 3-stage cp.async pipeline, 8 warps (4x2), warp 32x64.
#define LDA 36
#define LDB 132
#define ASZ (128 * LDA)      // 4608 floats
#define BSZ (32 * LDB)       // 4224 floats
#define STGSZ (ASZ + BSZ)    // 8832 floats
#define NSTAGE 3
#define GEMM_SMEM (NSTAGE * STGSZ * 4)   // 105984 bytes

template <bool RELU, bool DUAL, bool POOL>
__device__ __forceinline__ void gemm_load_slab(
    const float* __restrict__ A, const float* __restrict__ B,
    float* sm, int slot, int k0, int tid, int m0, int n0, int M, int K) {
    float* smA = sm + slot * STGSZ;
    float* smB = smA + ASZ;
#pragma unroll
    for (int t = 0; t < 4; t++) {
        int j   = tid + t * 256;
        int row = j >> 3;
        int c4  = (j & 7) * 4;
        bool ok = (m0 + row < M);
        const float* gs = &A[ok ? ((size_t)(m0 + row) * K + k0 + c4) : 0];
        cp_async16z(&smA[row * LDA + c4], gs, ok ? 16 : 0);
    }
#pragma unroll
    for (int t = 0; t < 4; t++) {
        int j   = tid + t * 256;
        int row = j >> 5;
        int c4  = (j & 31) * 4;
        cp_async16(&smB[row * LDB + c4], &B[(size_t)(k0 + row) * 256 + n0 + c4]);
    }
}

template <bool RELU, bool DUAL, bool POOL>
__global__ __launch_bounds__(256)
void gemm_tc(const float* __restrict__ A, const float* __restrict__ B,
             const float* __restrict__ bias, float* __restrict__ C,
             float* __restrict__ C2, const float* __restrict__ epsp,
             const int* __restrict__ batch, float* __restrict__ psum,
             int M, int K) {
    extern __shared__ float sm[];

    int tid  = threadIdx.x;
    int wid  = tid >> 5;
    int lane = tid & 31;
    int wm = wid >> 1;
    int wn = wid & 1;
    int m0 = blockIdx.y * 128;
    int n0 = blockIdx.x * 128;

    wmma::fragment<wmma::accumulator, 16, 16, 8, float> acc[2][4];
#pragma unroll
    for (int i = 0; i < 2; i++)
#pragma unroll
        for (int j = 0; j < 4; j++) wmma::fill_fragment(acc[i][j], 0.0f);

    int iters = K >> 5;

    // prologue: fill NSTAGE-1 slabs
#pragma unroll
    for (int i = 0; i < NSTAGE - 1; i++) {
        if (i < iters)
            gemm_load_slab<RELU, DUAL, POOL>(A, B, sm, i, i * 32, tid, m0, n0, M, K);
        cp_commit();
    }

    for (int it = 0; it < iters; it++) {
        int pf = it + NSTAGE - 1;
        if (pf < iters)
            gemm_load_slab<RELU, DUAL, POOL>(A, B, sm, pf % NSTAGE, pf * 32, tid, m0, n0, M, K);
        cp_commit();
        cp_wait<NSTAGE - 1>();   // slab `it` ready
        __syncthreads();

        float* smA = sm + (it % NSTAGE) * STGSZ;
        float* smB = smA + ASZ;
#pragma unroll
        for (int ks = 0; ks < 4; ks++) {
            wmma::fragment<wmma::matrix_a, 16, 16, 8, wmma::precision::tf32,
                           wmma::row_major> af[2];
            wmma::fragment<wmma::matrix_b, 16, 16, 8, wmma::precision::tf32,
                           wmma::row_major> bf[4];
#pragma unroll
            for (int i = 0; i < 2; i++) {
                wmma::load_matrix_sync(af[i], &smA[(wm * 32 + i * 16) * LDA + ks * 8], LDA);
#pragma unroll
                for (int t = 0; t < af[i].num_elements; t++)
                    af[i].x[t] = wmma::__float_to_tf32(af[i].x[t]);
            }
#pragma unroll
            for (int j = 0; j < 4; j++)
                wmma::load_matrix_sync(bf[j], &smB[(ks * 8) * LDB + wn * 64 + j * 16], LDB);
#pragma unroll
            for (int i = 0; i < 2; i++)
#pragma unroll
                for (int j = 0; j < 4; j++)
                    wmma::mma_sync(acc[i][j], af[i], bf[j], acc[i][j]);
        }
        __syncthreads();
    }

    // ---- epilogue via per-warp smem staging (reuse pipeline smem) ----
    const int LDS_ = 20;
    float* St = sm + wid * (16 * LDS_);
    float scale = DUAL ? (1.0f + *epsp) : 1.0f;
#pragma unroll
    for (int i = 0; i < 2; i++)
#pragma unroll
        for (int j = 0; j < 4; j++) {
            wmma::store_matrix_sync(St, acc[i][j], LDS_, wmma::mem_row_major);
            __syncwarp();
            int r   = lane >> 1;
            int c   = (lane & 1) * 8;
            int row = m0 + wm * 32 + i * 16 + r;
            int col = n0 + wn * 64 + j * 16 + c;
            if (row < M) {
                float v[8];
#pragma unroll
                for (int u = 0; u < 8; u++) {
                    v[u] = St[r * LDS_ + c + u] + bias[col + u];
                    if (RELU) v[u] = fmaxf(v[u], 0.0f);
                }
                if (POOL) {
                    int g = batch[row];
                    float4* pp = (float4*)&psum[(size_t)g * 256 + col];
                    atomicAdd(&pp[0], make_float4(v[0], v[1], v[2], v[3]));
                    atomicAdd(&pp[1], make_float4(v[4], v[5], v[6], v[7]));
                } else {
                    float4* cp = (float4*)&C[(size_t)row * 256 + col];
                    cp[0] = make_float4(v[0], v[1], v[2], v[3]);
                    cp[1] = make_float4(v[4], v[5], v[6], v[7]);
                    if (DUAL) {
                        float4* cp2 = (float4*)&C2[(size_t)row * 256 + col];
                        cp2[0] = make_float4(v[0] * scale, v[1] * scale, v[2] * scale, v[3] * scale);
                        cp2[1] = make_float4(v[4] * scale, v[5] * scale, v[6] * scale, v[7] * scale);
                    }
                }
            }
            __syncwarp();
        }
}

// ---------------- final: mean, linear [256->10], log_softmax ----------------
__global__ void final_k(const float* __restrict__ psum, const float* __restrict__ cnt,
                        const float* __restrict__ Wlin, const float* __restrict__ blin,
                        float* __restrict__ out) {
    int g = blockIdx.x;
    int lane = threadIdx.x;
    float inv = 1.0f / fmaxf(cnt[g], 1.0f);
    float acc[FOUT];
#pragma unroll
    for (int o = 0; o < FOUT; o++) acc[o] = 0.0f;
    for (int h = lane; h < FH; h += 32) {
        float p = psum[g * FH + h] * inv;
#pragma unroll
        for (int o = 0; o < FOUT; o++) acc[o] += p * Wlin[h * FOUT + o];
    }
#pragma unroll
    for (int off = 16; off > 0; off >>= 1)
#pragma unroll
        for (int o = 0; o < FOUT; o++)
            acc[o] += __shfl_down_sync(0xffffffffu, acc[o], off);
    if (lane == 0) {
        float z[FOUT];
        float m = -1e30f;
#pragma unroll
        for (int o = 0; o < FOUT; o++) { z[o] = acc[o] + blin[o]; m = fmaxf(m, z[o]); }
        float s = 0.0f;
#pragma unroll
        for (int o = 0; o < FOUT; o++) s += __expf(z[o] - m);
        float l = logf(s);
#pragma unroll
        for (int o = 0; o < FOUT; o++) out[g * FOUT + o] = z[o] - m - l;
    }
}

// ---------------- launcher ----------------
extern "C" void kernel_launch(void* const* d_in, const int* in_sizes, int n_in,
                              void* d_out, int out_size) {
    const float* x     = (const float*)d_in[0];
    const int*   ei    = (const int*)  d_in[1];
    const int*   batch = (const int*)  d_in[2];
    const float* eps1  = (const float*)d_in[3];
    const float* W1a   = (const float*)d_in[4];
    const float* b1a   = (const float*)d_in[5];
    const float* W1b   = (const float*)d_in[6];
    const float* b1b   = (const float*)d_in[7];
    const float* eps2  = (const float*)d_in[8];
    const float* W2a   = (const float*)d_in[9];
    const float* b2a   = (const float*)d_in[10];
    const float* W2b   = (const float*)d_in[11];
    const float* b2b   = (const float*)d_in[12];
    const float* Wlin  = (const float*)d_in[13];
    const float* blin  = (const float*)d_in[14];
    float* out = (float*)d_out;

    void *p_agg1, *p_t1, *p_h, *p_agg2, *p_t2, *p_psum, *p_cnt;
    void *p_w1a, *p_w1b, *p_w2a, *p_w2b;
    cudaGetSymbolAddress(&p_agg1, g_agg1);
    cudaGetSymbolAddress(&p_t1,   g_t1);
    cudaGetSymbolAddress(&p_h,    g_h);
    cudaGetSymbolAddress(&p_agg2, g_agg2);
    cudaGetSymbolAddress(&p_t2,   g_t2);
    cudaGetSymbolAddress(&p_psum, g_psum);
    cudaGetSymbolAddress(&p_cnt,  g_cnt);
    cudaGetSymbolAddress(&p_w1a, g_W1a_t);
    cudaGetSymbolAddress(&p_w1b, g_W1b_t);
    cudaGetSymbolAddress(&p_w2a, g_W2a_t);
    cudaGetSymbolAddress(&p_w2b, g_W2b_t);
    float4* agg1 = (float4*)p_agg1;
    float4* t1   = (float4*)p_t1;
    float4* h    = (float4*)p_h;
    float4* agg2 = (float4*)p_agg2;
    float4* t2   = (float4*)p_t2;
    float*  psum = (float*)p_psum;
    float*  cnt  = (float*)p_cnt;
    float*  W1a_t = (float*)p_w1a;
    float*  W1b_t = (float*)p_w1b;
    float*  W2a_t = (float*)p_w2a;
    float*  W2b_t = (float*)p_w2b;

    cudaFuncSetAttribute(gemm_tc<true,  false, false>,
                         cudaFuncAttributeMaxDynamicSharedMemorySize, GEMM_SMEM);
    cudaFuncSetAttribute(gemm_tc<true,  true,  false>,
                         cudaFuncAttributeMaxDynamicSharedMemorySize, GEMM_SMEM);
    cudaFuncSetAttribute(gemm_tc<false, false, true>,
                         cudaFuncAttributeMaxDynamicSharedMemorySize, GEMM_SMEM);

    const int* src = ei;
    const int* dst = ei + NEDGE;
    const int T = 256;

    // pre-convert weights to tf32
    wconv_k<<<(FIN * FH + T - 1) / T, T>>>(W1a, W1a_t, FIN * FH);
    wconv_k<<<(FH * FH + T - 1) / T, T>>>(W1b, W1b_t, FH * FH);
    wconv_k<<<(FH * FH + T - 1) / T, T>>>(W2a, W2a_t, FH * FH);
    wconv_k<<<(FH * FH + T - 1) / T, T>>>(W2b, W2b_t, FH * FH);

    // agg1 = (1+eps1)*x + scatter x[src]
    {
        int total = NNODE * (FIN / 4);
        scale_copy_k<<<(total + T - 1) / T, T>>>((const float4*)x, eps1, agg1, total);
    }
    {
        int total = NEDGE * (FIN / 4);
        scatter_k<<<(total + T - 1) / T, T>>>((const float4*)x, src, dst, agg1,
                                              total, 5, 31, FIN / 4);
    }

    dim3 gdim(2, (NNODE + 127) / 128);
    // t1 = relu(agg1 @ W1a + b1a)
    gemm_tc<true, false, false><<<gdim, 256, GEMM_SMEM>>>(
        (const float*)agg1, W1a_t, b1a, (float*)t1, nullptr, nullptr,
        nullptr, nullptr, NNODE, FIN);
    // h = relu(t1 @ W1b + b1b); agg2 = (1+eps2)*h (dual store)
    gemm_tc<true, true, false><<<gdim, 256, GEMM_SMEM>>>(
        (const float*)t1, W1b_t, b1b, (float*)h, (float*)agg2, eps2,
        nullptr, nullptr, NNODE, FH);
    // agg2 += scatter h[src]
    {
        int total = NEDGE * (FH / 4);
        scatter_k<<<(total + T - 1) / T, T>>>(h, src, dst, agg2, total, 6, 63, FH / 4);
    }
    // t2 = relu(agg2 @ W2a + b2a)
    gemm_tc<true, false, false><<<gdim, 256, GEMM_SMEM>>>(
        (const float*)agg2, W2a_t, b2a, (float*)t2, nullptr, nullptr,
        nullptr, nullptr, NNODE, FH);

    // zero pooling buffers + counts (before the fused-pool GEMM)
    zero_k<<<(NG * FH + T - 1) / T, T>>>(psum, NG * FH);
    zero_k<<<(NG + T - 1) / T, T>>>(cnt, NG);
    count_k<<<(NNODE + T - 1) / T, T>>>(batch, cnt);

    // h2 = t2 @ W2b + b2b, fused global-mean-pool partial sums into psum
    gemm_tc<false, false, true><<<gdim, 256, GEMM_SMEM>>>(
        (const float*)t2, W2b_t, b2b, nullptr, nullptr, nullptr,
        batch, psum, NNODE, FH);

    // mean + linear + log_softmax
    final_k<<<NG, 32>>>(psum, cnt, Wlin, blin, out);
}

// round 6
// speedup vs baseline: 1.9298x; 1.2421x over previous
#include <cuda_runtime.h>
#include <mma.h>
#include <cstdint>

using namespace nvcuda;

// Problem constants (fixed by the dataset)
#define NNODE 50000
#define NEDGE 800000
#define FIN   128
#define FH    256
#define FOUT  10
#define NG    512

// ---------------- scratch (device globals; no allocation) ----------------
__device__ float4 g_agg1[NNODE * (FIN / 4)];
__device__ float4 g_t1  [NNODE * (FH  / 4)];
__device__ float4 g_h   [NNODE * (FH  / 4)];
__device__ float4 g_agg2[NNODE * (FH  / 4)];
__device__ float4 g_t2  [NNODE * (FH  / 4)];
__device__ float4 g_psum[NG * (FH / 4)];
__device__ float  g_cnt [NG];
// CSR for incoming edges
__device__ int    g_deg [NNODE];
__device__ int    g_off [NNODE + 1];
__device__ int    g_cur [NNODE];
__device__ int    g_eidx[NEDGE];
// tf32-preconverted weights
__device__ float  g_W1a_t[FIN * FH];
__device__ float  g_W1b_t[FH * FH];
__device__ float  g_W2a_t[FH * FH];
__device__ float  g_W2b_t[FH * FH];

// ---------------- cp.async helpers ----------------
__device__ __forceinline__ void cp_async16(float* dst, const float* src) {
    uint32_t s = (uint32_t)__cvta_generic_to_shared(dst);
    asm volatile("cp.async.cg.shared.global [%0], [%1], 16;\n" :: "r"(s), "l"(src));
}
__device__ __forceinline__ void cp_async16z(float* dst, const float* src, int szbytes) {
    uint32_t s = (uint32_t)__cvta_generic_to_shared(dst);
    asm volatile("cp.async.cg.shared.global [%0], [%1], 16, %2;\n"
                 :: "r"(s), "l"(src), "r"(szbytes));
}
__device__ __forceinline__ void cp_commit() { asm volatile("cp.async.commit_group;\n"); }
template <int N>
__device__ __forceinline__ void cp_wait() { asm volatile("cp.async.wait_group %0;\n" :: "n"(N)); }

// ---------------- small utility kernels ----------------
__global__ void zero_k(float* __restrict__ p, int n) {
    int i = blockIdx.x * blockDim.x + threadIdx.x;
    if (i < n) p[i] = 0.0f;
}
__global__ void zeroi_k(int* __restrict__ p, int n) {
    int i = blockIdx.x * blockDim.x + threadIdx.x;
    if (i < n) p[i] = 0;
}
__global__ void wconv_k(const float* __restrict__ src, float* __restrict__ dst, int n) {
    int i = blockIdx.x * blockDim.x + threadIdx.x;
    if (i < n) dst[i] = wmma::__float_to_tf32(src[i]);
}

// ---------------- CSR build ----------------
__global__ void hist_k(const int* __restrict__ dst, int* __restrict__ deg) {
    int e = blockIdx.x * blockDim.x + threadIdx.x;
    if (e < NEDGE) atomicAdd(&deg[dst[e]], 1);
}

// exclusive prefix sum over NNODE entries, single block 1024 threads, warp-scan based
__global__ void scan_k(const int* __restrict__ deg, int* __restrict__ off) {
    __shared__ int wsum[32];
    __shared__ int carry;
    int tid  = threadIdx.x;
    int lane = tid & 31;
    int w    = tid >> 5;
    if (tid == 0) carry = 0;
    __syncthreads();
    for (int base = 0; base < NNODE; base += 1024) {
        int i = base + tid;
        int v = (i < NNODE) ? deg[i] : 0;
        // inclusive warp scan
        int s = v;
#pragma unroll
        for (int o = 1; o < 32; o <<= 1) {
            int t = __shfl_up_sync(0xffffffffu, s, o);
            if (lane >= o) s += t;
        }
        if (lane == 31) wsum[w] = s;
        __syncthreads();
        if (w == 0) {
            int ws = (lane < 32) ? wsum[lane] : 0;
#pragma unroll
            for (int o = 1; o < 32; o <<= 1) {
                int t = __shfl_up_sync(0xffffffffu, ws, o);
                if (lane >= o) ws += t;
            }
            wsum[lane] = ws;
        }
        __syncthreads();
        int wpre = (w == 0) ? 0 : wsum[w - 1];
        if (i < NNODE) off[i] = carry + wpre + s - v;   // exclusive
        __syncthreads();
        if (tid == 0) carry += wsum[31];
        __syncthreads();
    }
    if (threadIdx.x == 0) off[NNODE] = carry;
}

__global__ void copyoff_k(const int* __restrict__ off, int* __restrict__ cur) {
    int i = blockIdx.x * blockDim.x + threadIdx.x;
    if (i < NNODE) cur[i] = off[i];
}

__global__ void fill_k(const int* __restrict__ src, const int* __restrict__ dst,
                       int* __restrict__ cur, int* __restrict__ eidx) {
    int e = blockIdx.x * blockDim.x + threadIdx.x;
    if (e >= NEDGE) return;
    int p = atomicAdd(&cur[dst[e]], 1);
    eidx[p] = src[e];
}

// ---------------- CSR gather aggregation ----------------
// out[i] = (1+eps)*feat[i] + sum_{j in in(i)} feat[j]
// F4SHIFT: log2 of float4-lanes per node (5 for FIN=128, 6 for FH=256).
template <int F4SHIFT>
__global__ void agg_k(const float4* __restrict__ feat, const float* __restrict__ eps,
                      const int* __restrict__ off, const int* __restrict__ eidx,
                      float4* __restrict__ out) {
    const int lanes = 1 << F4SHIFT;
    int node = blockIdx.x * (256 >> F4SHIFT) + (threadIdx.x >> F4SHIFT);
    int f    = threadIdx.x & (lanes - 1);
    if (node >= NNODE) return;
    float s = 1.0f + *eps;
    float4 x = feat[((size_t)node << F4SHIFT) + f];
    float4 a0 = make_float4(x.x * s, x.y * s, x.z * s, x.w * s);
    float4 a1 = make_float4(0.f, 0.f, 0.f, 0.f);
    float4 a2 = make_float4(0.f, 0.f, 0.f, 0.f);
    float4 a3 = make_float4(0.f, 0.f, 0.f, 0.f);
    int b = off[node], e = off[node + 1];
    int j = b;
    // 4-way unrolled for MLP
    for (; j + 3 < e; j += 4) {
        int s0 = eidx[j], s1 = eidx[j + 1], s2 = eidx[j + 2], s3 = eidx[j + 3];
        float4 v0 = feat[((size_t)s0 << F4SHIFT) + f];
        float4 v1 = feat[((size_t)s1 << F4SHIFT) + f];
        float4 v2 = feat[((size_t)s2 << F4SHIFT) + f];
        float4 v3 = feat[((size_t)s3 << F4SHIFT) + f];
        a0.x += v0.x; a0.y += v0.y; a0.z += v0.z; a0.w += v0.w;
        a1.x += v1.x; a1.y += v1.y; a1.z += v1.z; a1.w += v1.w;
        a2.x += v2.x; a2.y += v2.y; a2.z += v2.z; a2.w += v2.w;
        a3.x += v3.x; a3.y += v3.y; a3.z += v3.z; a3.w += v3.w;
    }
    for (; j < e; j++) {
        float4 v = feat[((size_t)eidx[j] << F4SHIFT) + f];
        a0.x += v.x; a0.y += v.y; a0.z += v.z; a0.w += v.w;
    }
    a0.x += a1.x + a2.x + a3.x;
    a0.y += a1.y + a2.y + a3.y;
    a0.z += a1.z + a2.z + a3.z;
    a0.w += a1.w + a2.w + a3.w;
    out[((size_t)node << F4SHIFT) + f] = a0;
}

__global__ void count_k(const int* __restrict__ batch, float* __restrict__ cnt) {
    int i = blockIdx.x * blockDim.x + threadIdx.x;
    if (i < NNODE) atomicAdd(&cnt[batch[i]], 1.0f);
}

// ---------------- Pipelined TF32 tensor-core GEMM (R4 design, known good) ----------------
#define LDA 36
#define LDB 132
#define ASZ (128 * LDA)
#define BSZ (32 * LDB)
#define STGSZ (ASZ + BSZ)
#define NSTAGE 3
#define GEMM_SMEM (NSTAGE * STGSZ * 4)

template <bool RELU, bool POOL>
__device__ __forceinline__ void gemm_load_slab(
    const float* __restrict__ A, const float* __restrict__ B,
    float* sm, int slot, int k0, int tid, int m0, int n0, int M, int K) {
    float* smA = sm + slot * STGSZ;
    float* smB = smA + ASZ;
#pragma unroll
    for (int t = 0; t < 4; t++) {
        int j   = tid + t * 256;
        int row = j >> 3;
        int c4  = (j & 7) * 4;
        bool ok = (m0 + row < M);
        const float* gs = &A[ok ? ((size_t)(m0 + row) * K + k0 + c4) : 0];
        cp_async16z(&smA[row * LDA + c4], gs, ok ? 16 : 0);
    }
#pragma unroll
    for (int t = 0; t < 4; t++) {
        int j   = tid + t * 256;
        int row = j >> 5;
        int c4  = (j & 31) * 4;
        cp_async16(&smB[row * LDB + c4], &B[(size_t)(k0 + row) * 256 + n0 + c4]);
    }
}

template <bool RELU, bool POOL>
__global__ __launch_bounds__(256)
void gemm_tc(const float* __restrict__ A, const float* __restrict__ B,
             const float* __restrict__ bias, float* __restrict__ C,
             const int* __restrict__ batch, float* __restrict__ psum,
             int M, int K) {
    extern __shared__ float sm[];

    int tid  = threadIdx.x;
    int wid  = tid >> 5;
    int lane = tid & 31;
    int wm = wid >> 1;
    int wn = wid & 1;
    int m0 = blockIdx.y * 128;
    int n0 = blockIdx.x * 128;

    wmma::fragment<wmma::accumulator, 16, 16, 8, float> acc[2][4];
#pragma unroll
    for (int i = 0; i < 2; i++)
#pragma unroll
        for (int j = 0; j < 4; j++) wmma::fill_fragment(acc[i][j], 0.0f);

    int iters = K >> 5;

#pragma unroll
    for (int i = 0; i < NSTAGE - 1; i++) {
        if (i < iters)
            gemm_load_slab<RELU, POOL>(A, B, sm, i, i * 32, tid, m0, n0, M, K);
        cp_commit();
    }

    for (int it = 0; it < iters; it++) {
        int pf = it + NSTAGE - 1;
        if (pf < iters)
            gemm_load_slab<RELU, POOL>(A, B, sm, pf % NSTAGE, pf * 32, tid, m0, n0, M, K);
        cp_commit();
        cp_wait<NSTAGE - 1>();
        __syncthreads();

        float* smA = sm + (it % NSTAGE) * STGSZ;
        float* smB = smA + ASZ;
#pragma unroll
        for (int ks = 0; ks < 4; ks++) {
            wmma::fragment<wmma::matrix_a, 16, 16, 8, wmma::precision::tf32,
                           wmma::row_major> af[2];
            wmma::fragment<wmma::matrix_b, 16, 16, 8, wmma::precision::tf32,
                           wmma::row_major> bf[4];
#pragma unroll
            for (int i = 0; i < 2; i++) {
                wmma::load_matrix_sync(af[i], &smA[(wm * 32 + i * 16) * LDA + ks * 8], LDA);
#pragma unroll
                for (int t = 0; t < af[i].num_elements; t++)
                    af[i].x[t] = wmma::__float_to_tf32(af[i].x[t]);
            }
#pragma unroll
            for (int j = 0; j < 4; j++)
                wmma::load_matrix_sync(bf[j], &smB[(ks * 8) * LDB + wn * 64 + j * 16], LDB);
#pragma unroll
            for (int i = 0; i < 2; i++)
#pragma unroll
                for (int j = 0; j < 4; j++)
                    wmma::mma_sync(acc[i][j], af[i], bf[j], acc[i][j]);
        }
        __syncthreads();
    }

    // ---- epilogue ----
    const int LDS_ = 20;
    float* St = sm + wid * (16 * LDS_);
#pragma unroll
    for (int i = 0; i < 2; i++)
#pragma unroll
        for (int j = 0; j < 4; j++) {
            wmma::store_matrix_sync(St, acc[i][j], LDS_, wmma::mem_row_major);
            __syncwarp();
            int r   = lane >> 1;
            int c   = (lane & 1) * 8;
            int row = m0 + wm * 32 + i * 16 + r;
            int col = n0 + wn * 64 + j * 16 + c;
            if (row < M) {
                float v[8];
#pragma unroll
                for (int u = 0; u < 8; u++) {
                    v[u] = St[r * LDS_ + c + u] + bias[col + u];
                    if (RELU) v[u] = fmaxf(v[u], 0.0f);
                }
                if (POOL) {
                    int g = batch[row];
                    float4* pp = (float4*)&psum[(size_t)g * 256 + col];
                    atomicAdd(&pp[0], make_float4(v[0], v[1], v[2], v[3]));
                    atomicAdd(&pp[1], make_float4(v[4], v[5], v[6], v[7]));
                } else {
                    float4* cp = (float4*)&C[(size_t)row * 256 + col];
                    cp[0] = make_float4(v[0], v[1], v[2], v[3]);
                    cp[1] = make_float4(v[4], v[5], v[6], v[7]);
                }
            }
            __syncwarp();
        }
}

// ---------------- final: mean, linear [256->10], log_softmax ----------------
__global__ void final_k(const float* __restrict__ psum, const float* __restrict__ cnt,
                        const float* __restrict__ Wlin, const float* __restrict__ blin,
                        float* __restrict__ out) {
    int g = blockIdx.x;
    int lane = threadIdx.x;
    float inv = 1.0f / fmaxf(cnt[g], 1.0f);
    float acc[FOUT];
#pragma unroll
    for (int o = 0; o < FOUT; o++) acc[o] = 0.0f;
    for (int h = lane; h < FH; h += 32) {
        float p = psum[g * FH + h] * inv;
#pragma unroll
        for (int o = 0; o < FOUT; o++) acc[o] += p * Wlin[h * FOUT + o];
    }
#pragma unroll
    for (int off = 16; off > 0; off >>= 1)
#pragma unroll
        for (int o = 0; o < FOUT; o++)
            acc[o] += __shfl_down_sync(0xffffffffu, acc[o], off);
    if (lane == 0) {
        float z[FOUT];
        float m = -1e30f;
#pragma unroll
        for (int o = 0; o < FOUT; o++) { z[o] = acc[o] + blin[o]; m = fmaxf(m, z[o]); }
        float s = 0.0f;
#pragma unroll
        for (int o = 0; o < FOUT; o++) s += __expf(z[o] - m);
        float l = logf(s);
#pragma unroll
        for (int o = 0; o < FOUT; o++) out[g * FOUT + o] = z[o] - m - l;
    }
}

// ---------------- launcher ----------------
extern "C" void kernel_launch(void* const* d_in, const int* in_sizes, int n_in,
                              void* d_out, int out_size) {
    const float* x     = (const float*)d_in[0];
    const int*   ei    = (const int*)  d_in[1];
    const int*   batch = (const int*)  d_in[2];
    const float* eps1  = (const float*)d_in[3];
    const float* W1a   = (const float*)d_in[4];
    const float* b1a   = (const float*)d_in[5];
    const float* W1b   = (const float*)d_in[6];
    const float* b1b   = (const float*)d_in[7];
    const float* eps2  = (const float*)d_in[8];
    const float* W2a   = (const float*)d_in[9];
    const float* b2a   = (const float*)d_in[10];
    const float* W2b   = (const float*)d_in[11];
    const float* b2b   = (const float*)d_in[12];
    const float* Wlin  = (const float*)d_in[13];
    const float* blin  = (const float*)d_in[14];
    float* out = (float*)d_out;

    void *p_agg1, *p_t1, *p_h, *p_agg2, *p_t2, *p_psum, *p_cnt;
    void *p_deg, *p_off, *p_cur, *p_eidx;
    void *p_w1a, *p_w1b, *p_w2a, *p_w2b;
    cudaGetSymbolAddress(&p_agg1, g_agg1);
    cudaGetSymbolAddress(&p_t1,   g_t1);
    cudaGetSymbolAddress(&p_h,    g_h);
    cudaGetSymbolAddress(&p_agg2, g_agg2);
    cudaGetSymbolAddress(&p_t2,   g_t2);
    cudaGetSymbolAddress(&p_psum, g_psum);
    cudaGetSymbolAddress(&p_cnt,  g_cnt);
    cudaGetSymbolAddress(&p_deg,  g_deg);
    cudaGetSymbolAddress(&p_off,  g_off);
    cudaGetSymbolAddress(&p_cur,  g_cur);
    cudaGetSymbolAddress(&p_eidx, g_eidx);
    cudaGetSymbolAddress(&p_w1a, g_W1a_t);
    cudaGetSymbolAddress(&p_w1b, g_W1b_t);
    cudaGetSymbolAddress(&p_w2a, g_W2a_t);
    cudaGetSymbolAddress(&p_w2b, g_W2b_t);
    float4* agg1 = (float4*)p_agg1;
    float4* t1   = (float4*)p_t1;
    float4* h    = (float4*)p_h;
    float4* agg2 = (float4*)p_agg2;
    float4* t2   = (float4*)p_t2;
    float*  psum = (float*)p_psum;
    float*  cnt  = (float*)p_cnt;
    int* deg  = (int*)p_deg;
    int* off  = (int*)p_off;
    int* cur  = (int*)p_cur;
    int* eidx = (int*)p_eidx;
    float*  W1a_t = (float*)p_w1a;
    float*  W1b_t = (float*)p_w1b;
    float*  W2a_t = (float*)p_w2a;
    float*  W2b_t = (float*)p_w2b;

    cudaFuncSetAttribute(gemm_tc<true,  false>,
                         cudaFuncAttributeMaxDynamicSharedMemorySize, GEMM_SMEM);
    cudaFuncSetAttribute(gemm_tc<false, true>,
                         cudaFuncAttributeMaxDynamicSharedMemorySize, GEMM_SMEM);

    const int* src = ei;
    const int* dst = ei + NEDGE;
    const int T = 256;

    // ---- CSR build (incoming edges per node) ----
    zeroi_k<<<(NNODE + T - 1) / T, T>>>(deg, NNODE);
    hist_k<<<(NEDGE + T - 1) / T, T>>>(dst, deg);
    scan_k<<<1, 1024>>>(deg, off);
    copyoff_k<<<(NNODE + T - 1) / T, T>>>(off, cur);
    fill_k<<<(NEDGE + T - 1) / T, T>>>(src, dst, cur, eidx);

    // ---- weights to tf32 ----
    wconv_k<<<(FIN * FH + T - 1) / T, T>>>(W1a, W1a_t, FIN * FH);
    wconv_k<<<(FH * FH + T - 1) / T, T>>>(W1b, W1b_t, FH * FH);
    wconv_k<<<(FH * FH + T - 1) / T, T>>>(W2a, W2a_t, FH * FH);
    wconv_k<<<(FH * FH + T - 1) / T, T>>>(W2b, W2b_t, FH * FH);

    // ---- layer 1: agg1 = (1+eps1)*x + gather; t1 = relu(agg1@W1a+b1a); h = relu(t1@W1b+b1b)
    agg_k<5><<<(NNODE * 32 + T - 1) / T, T>>>((const float4*)x, eps1, off, eidx, agg1);

    dim3 gdim(2, (NNODE + 127) / 128);
    gemm_tc<true, false><<<gdim, 256, GEMM_SMEM>>>(
        (const float*)agg1, W1a_t, b1a, (float*)t1, nullptr, nullptr, NNODE, FIN);
    gemm_tc<true, false><<<gdim, 256, GEMM_SMEM>>>(
        (const float*)t1, W1b_t, b1b, (float*)h, nullptr, nullptr, NNODE, FH);

    // ---- layer 2: agg2 = (1+eps2)*h + gather; t2 = relu(agg2@W2a+b2a)
    agg_k<6><<<(NNODE * 64 + T - 1) / T, T>>>(h, eps2, off, eidx, agg2);
    gemm_tc<true, false><<<gdim, 256, GEMM_SMEM>>>(
        (const float*)agg2, W2a_t, b2a, (float*)t2, nullptr, nullptr, NNODE, FH);

    // ---- pooling setup ----
    zero_k<<<(NG * FH + T - 1) / T, T>>>(psum, NG * FH);
    zero_k<<<(NG + T - 1) / T, T>>>(cnt, NG);
    count_k<<<(NNODE + T - 1) / T, T>>>(batch, cnt);

    // h2 = t2 @ W2b + b2b fused with global-mean-pool partial sums
    gemm_tc<false, true><<<gdim, 256, GEMM_SMEM>>>(
        (const float*)t2, W2b_t, b2b, nullptr, batch, psum, NNODE, FH);

    // mean + linear + log_softmax
    final_k<<<NG, 32>>>(psum, cnt, Wlin, blin, out);
}